// round 1
// baseline (speedup 1.0000x reference)
#include <cuda_runtime.h>
#include <cstdint>
#include <cstddef>

#define NU 100000
#define NVV 100000
#define DD 128
#define RR 5
#define OO 64
#define EE 640000
#define NW 320   /* RR * OO */

// ---------------------------------------------------------------------------
// Scratch (static device globals; no allocation allowed in kernel_launch)
// ---------------------------------------------------------------------------
__device__ float g_tmpU[(size_t)NU * NW];   // x_u @ WcatU  [NU][320]
__device__ float g_tmpV[(size_t)NVV * NW];  // x_v @ WcatV  [NV][320]
__device__ float g_WcatU[DD * NW];          // cumsum weights_u, [d][r*64+o]
__device__ float g_WcatV[DD * NW];

// ---------------------------------------------------------------------------
// Kernel: ordinal cumsum of weights into concatenated [128 x 320] B matrix
// ---------------------------------------------------------------------------
__global__ void cumsum_kernel(const float* __restrict__ wu,
                              const float* __restrict__ wv,
                              float* __restrict__ WU,
                              float* __restrict__ WV)
{
    int i = blockIdx.x * blockDim.x + threadIdx.x;   // (d*64 + o)
    if (i >= DD * OO) return;
    const float* w = blockIdx.y ? wv : wu;
    float*       W = blockIdx.y ? WV : WU;
    int d = i >> 6, o = i & 63;
    float s = 0.f;
#pragma unroll
    for (int r = 0; r < RR; r++) {
        s += w[r * DD * OO + i];
        W[d * NW + r * OO + o] = s;
    }
}

// ---------------------------------------------------------------------------
// Kernel: SGEMM  C[M,320] = A[M,128] @ W[128,320], fp32, FFMA2 inner loop.
// BM=128, BN=64 (gridDim.y selects 64-col relation group), BK=128 (full K).
// 128 threads, 8x8 thread tile (8 rows x 4 f32x2 col-pairs).
// ---------------------------------------------------------------------------
#define GEMM_SMEM_FLOATS (128 * 129 + 128 * 64)
#define GEMM_SMEM_BYTES  (GEMM_SMEM_FLOATS * 4)

__global__ void __launch_bounds__(128, 2)
gemm_kernel(const float* __restrict__ A, const float* __restrict__ W,
            float* __restrict__ C, int M)
{
    extern __shared__ float smem[];
    float* As = smem;               // [k][m], row stride 129 (pad kills conflicts)
    float* Bs = smem + 128 * 129;   // [k][n], 64 wide

    const int tid = threadIdx.x;
    const int m0  = blockIdx.x * 128;
    const int g   = blockIdx.y;     // relation group: cols g*64 .. g*64+63

    // Load B tile: 128x64 from W[k][g*64+n]  (2048 float4)
#pragma unroll
    for (int i = tid; i < 2048; i += 128) {
        int k = i >> 4, n4 = (i & 15) << 2;
        *(float4*)&Bs[k * 64 + n4] = *(const float4*)&W[k * NW + g * 64 + n4];
    }
    // Load A tile transposed into As[k][m] (coalesced 512B row reads)
#pragma unroll
    for (int i = tid; i < 4096; i += 128) {
        int m = i >> 5, k4 = (i & 31) << 2;
        float4 v = make_float4(0.f, 0.f, 0.f, 0.f);
        if (m0 + m < M) v = *(const float4*)&A[(size_t)(m0 + m) * DD + k4];
        As[(k4 + 0) * 129 + m] = v.x;
        As[(k4 + 1) * 129 + m] = v.y;
        As[(k4 + 2) * 129 + m] = v.z;
        As[(k4 + 3) * 129 + m] = v.w;
    }
    __syncthreads();

    const int tx = (tid & 7) << 3;   // col offset within 64 (8 cols / thread)
    const int ty = (tid >> 3) << 3;  // row offset within 128 (8 rows / thread)

    unsigned long long acc[8][4];
#pragma unroll
    for (int i = 0; i < 8; i++)
#pragma unroll
        for (int j = 0; j < 4; j++) acc[i][j] = 0ull;

#pragma unroll 4
    for (int k = 0; k < 128; k++) {
        const unsigned long long* bp =
            (const unsigned long long*)&Bs[k * 64 + tx];
        unsigned long long b0 = bp[0], b1 = bp[1], b2 = bp[2], b3 = bp[3];
        const float* ap = &As[k * 129 + ty];
#pragma unroll
        for (int i = 0; i < 8; i++) {
            unsigned long long a2;
            asm("mov.b64 %0, {%1, %1};" : "=l"(a2) : "r"(__float_as_uint(ap[i])));
            asm("fma.rn.f32x2 %0, %1, %2, %0;" : "+l"(acc[i][0]) : "l"(a2), "l"(b0));
            asm("fma.rn.f32x2 %0, %1, %2, %0;" : "+l"(acc[i][1]) : "l"(a2), "l"(b1));
            asm("fma.rn.f32x2 %0, %1, %2, %0;" : "+l"(acc[i][2]) : "l"(a2), "l"(b2));
            asm("fma.rn.f32x2 %0, %1, %2, %0;" : "+l"(acc[i][3]) : "l"(a2), "l"(b3));
        }
    }

    // Store C (packed f32x2 pairs are bit-identical to two adjacent floats)
#pragma unroll
    for (int i = 0; i < 8; i++) {
        int m = m0 + ty + i;
        if (m < M) {
            unsigned long long* cp =
                (unsigned long long*)&C[(size_t)m * NW + g * 64 + tx];
            cp[0] = acc[i][0];
            cp[1] = acc[i][1];
            cp[2] = acc[i][2];
            cp[3] = acc[i][3];
        }
    }
}

// ---------------------------------------------------------------------------
// Kernel: SpMM scatter. One 16-lane group per edge: gather 64 floats of
// tmp[col], scale by val, red.global.add.v4.f32 into z[row].
// ---------------------------------------------------------------------------
__global__ void spmm_kernel(const int* __restrict__ rows,
                            const int* __restrict__ cols,
                            const float* __restrict__ vals,
                            const float* __restrict__ tmp, int roff,
                            float* __restrict__ z)
{
    int gt = blockIdx.x * blockDim.x + threadIdx.x;
    int e = gt >> 4;
    if (e >= EE) return;
    int lane = (gt & 15) << 2;
    int   row = __ldg(rows + e);
    int   col = __ldg(cols + e);
    float val = __ldg(vals + e);
    float4 t = *(const float4*)(tmp + (size_t)col * NW + roff + lane);
    float* dst = z + (size_t)row * OO + lane;
    asm volatile("red.global.add.v4.f32 [%0], {%1, %2, %3, %4};"
                 :: "l"(dst),
                    "f"(t.x * val), "f"(t.y * val), "f"(t.z * val), "f"(t.w * val)
                 : "memory");
}

// ---------------------------------------------------------------------------
// Kernels: zero init and final in-place ReLU on d_out
// ---------------------------------------------------------------------------
__global__ void zero_kernel(float4* __restrict__ p, int n4)
{
    int i = blockIdx.x * blockDim.x + threadIdx.x;
    if (i < n4) p[i] = make_float4(0.f, 0.f, 0.f, 0.f);
}

__global__ void relu_kernel(float4* __restrict__ p, int n4)
{
    int i = blockIdx.x * blockDim.x + threadIdx.x;
    if (i < n4) {
        float4 v = p[i];
        v.x = fmaxf(v.x, 0.f);
        v.y = fmaxf(v.y, 0.f);
        v.z = fmaxf(v.z, 0.f);
        v.w = fmaxf(v.w, 0.f);
        p[i] = v;
    }
}

// ---------------------------------------------------------------------------
// kernel_launch
// inputs: x_u, x_v, sup_rows, sup_cols, sup_vals, weights_u, weights_v
// output: [relu(z_u) (NU*64) | relu(z_v) (NV*64)]  fp32
// ---------------------------------------------------------------------------
extern "C" void kernel_launch(void* const* d_in, const int* in_sizes, int n_in,
                              void* d_out, int out_size)
{
    const float* x_u  = (const float*)d_in[0];
    const float* x_v  = (const float*)d_in[1];
    const int*   srow = (const int*)d_in[2];
    const int*   scol = (const int*)d_in[3];
    const float* sval = (const float*)d_in[4];
    const float* wu   = (const float*)d_in[5];
    const float* wv   = (const float*)d_in[6];

    float* out = (float*)d_out;
    float* z_u = out;
    float* z_v = out + (size_t)NU * OO;

    float *tmpU, *tmpV, *WcU, *WcV;
    cudaGetSymbolAddress((void**)&tmpU, g_tmpU);
    cudaGetSymbolAddress((void**)&tmpV, g_tmpV);
    cudaGetSymbolAddress((void**)&WcU, g_WcatU);
    cudaGetSymbolAddress((void**)&WcV, g_WcatV);

    cudaFuncSetAttribute(gemm_kernel,
                         cudaFuncAttributeMaxDynamicSharedMemorySize,
                         GEMM_SMEM_BYTES);

    const int n4 = (NU * OO + NVV * OO) / 4;           // 3,200,000
    zero_kernel<<<(n4 + 255) / 256, 256>>>((float4*)out, n4);

    cumsum_kernel<<<dim3((DD * OO + 255) / 256, 2), 256>>>(wu, wv, WcU, WcV);

    const int gemm_gx = (NU + 127) / 128;              // 782
    const int spmm_blocks = (EE * 16 + 255) / 256;     // 40000

    // v-side GEMM then its SpMMs (tmpV hot in L2 for the gathers)
    gemm_kernel<<<dim3(gemm_gx, RR), 128, GEMM_SMEM_BYTES>>>(x_v, WcV, tmpV, NVV);
    for (int r = 0; r < RR; r++)
        spmm_kernel<<<spmm_blocks, 256>>>(srow + (size_t)r * EE,
                                          scol + (size_t)r * EE,
                                          sval + (size_t)r * EE,
                                          tmpV, r * OO, z_u);

    // u-side GEMM then its SpMMs
    gemm_kernel<<<dim3(gemm_gx, RR), 128, GEMM_SMEM_BYTES>>>(x_u, WcU, tmpU, NU);
    for (int r = 0; r < RR; r++)
        spmm_kernel<<<spmm_blocks, 256>>>(scol + (size_t)r * EE,
                                          srow + (size_t)r * EE,
                                          sval + (size_t)r * EE,
                                          tmpU, r * OO, z_v);

    relu_kernel<<<(n4 + 255) / 256, 256>>>((float4*)out, n4);
}

// round 4
// speedup vs baseline: 1.3605x; 1.3605x over previous
#include <cuda_runtime.h>
#include <cuda_bf16.h>
#include <cstdint>
#include <cstddef>

#define NU 100000
#define NVV 100000
#define DD 128
#define RR 5
#define OO 64
#define EE 640000

// ---------------------------------------------------------------------------
// Scratch (static device globals)
// ---------------------------------------------------------------------------
__device__ float g_tmpU[(size_t)RR * NU * OO];   // [r][n][64]
__device__ float g_tmpV[(size_t)RR * NVV * OO];  // [r][n][64]
// Pre-swizzled bf16 B images: per relation 32KB = hi 16KB | lo 16KB.
// Layout inside each half: row n (0..63) * 256B, 16B chunk c at (c ^ (n&7)).
__device__ unsigned char g_BimgU[RR * 32768];
__device__ unsigned char g_BimgV[RR * 32768];

// ---------------------------------------------------------------------------
// helpers
// ---------------------------------------------------------------------------
__device__ __forceinline__ uint32_t smem_u32(const void* p) {
    uint32_t a;
    asm("{ .reg .u64 t; cvta.to.shared.u64 t, %1; cvt.u32.u64 %0, t; }"
        : "=r"(a) : "l"(p));
    return a;
}
__device__ __forceinline__ void ldsm4(uint32_t addr, uint32_t& r0, uint32_t& r1,
                                      uint32_t& r2, uint32_t& r3) {
    asm volatile("ldmatrix.sync.aligned.m8n8.x4.shared.b16 {%0,%1,%2,%3}, [%4];"
                 : "=r"(r0), "=r"(r1), "=r"(r2), "=r"(r3) : "r"(addr));
}
__device__ __forceinline__ void mma_bf16(float* d, const uint32_t* a,
                                         uint32_t b0, uint32_t b1) {
    asm volatile(
        "mma.sync.aligned.m16n8k16.row.col.f32.bf16.bf16.f32 "
        "{%0,%1,%2,%3}, {%4,%5,%6,%7}, {%8,%9}, {%0,%1,%2,%3};"
        : "+f"(d[0]), "+f"(d[1]), "+f"(d[2]), "+f"(d[3])
        : "r"(a[0]), "r"(a[1]), "r"(a[2]), "r"(a[3]), "r"(b0), "r"(b1));
}

// ---------------------------------------------------------------------------
// cumsum weights + pack swizzled bf16 hi/lo B images
// thread i = d*64 + o  (k = d, n = o)
// ---------------------------------------------------------------------------
__global__ void cumsum_pack_kernel(const float* __restrict__ wu,
                                   const float* __restrict__ wv,
                                   unsigned char* __restrict__ imgU,
                                   unsigned char* __restrict__ imgV)
{
    int i = blockIdx.x * blockDim.x + threadIdx.x;
    if (i >= DD * OO) return;
    const float* w    = blockIdx.y ? wv : wu;
    unsigned char* im = blockIdx.y ? imgV : imgU;
    int k = i >> 6, n = i & 63;
    uint32_t off = (uint32_t)n * 256 + ((((k >> 3) ^ (n & 7))) << 4) + (k & 7) * 2;
    float s = 0.f;
#pragma unroll
    for (int r = 0; r < RR; r++) {
        s += w[r * DD * OO + i];
        __nv_bfloat16 h = __float2bfloat16_rn(s);
        __nv_bfloat16 l = __float2bfloat16_rn(s - __bfloat162float(h));
        *(__nv_bfloat16*)(im + r * 32768 + off)         = h;
        *(__nv_bfloat16*)(im + r * 32768 + 16384 + off) = l;
    }
}

// ---------------------------------------------------------------------------
// mma.sync split-bf16 GEMM: C[r][m][64] = A[m][128] @ Wcum[r], fp32 out.
// grid = (RR, rowTiles). CTA 128x64, 256 threads, warp tile 32x32.
// SMEM: Ah 32KB | Al 32KB | Bh 16KB | Bl 16KB = 96KB.
// ---------------------------------------------------------------------------
#define OFF_AH 0
#define OFF_AL 32768
#define OFF_BH 65536
#define OFF_BL 81920
#define GT_SMEM 98304

__global__ void __launch_bounds__(256, 2)
gemm_tc_kernel(const float* __restrict__ A,
               const unsigned char* __restrict__ Bimg,
               float* __restrict__ C, int M)
{
    extern __shared__ unsigned char smem[];
    const int tid  = threadIdx.x;
    const int wid  = tid >> 5;
    const int lane = tid & 31;
    const int g    = blockIdx.x;
    const int m0   = blockIdx.y * 128;

    // ---- A tile: load fp32, split into bf16 hi/lo, swizzled store ----
    for (int idx = tid; idx < 2048; idx += 256) {
        int m = idx >> 4, c = idx & 15, k0 = c << 3;
        float4 v0 = make_float4(0, 0, 0, 0), v1 = make_float4(0, 0, 0, 0);
        if (m0 + m < M) {
            const float* ap = A + (size_t)(m0 + m) * DD + k0;
            v0 = *(const float4*)ap;
            v1 = *(const float4*)(ap + 4);
        }
        float f[8] = {v0.x, v0.y, v0.z, v0.w, v1.x, v1.y, v1.z, v1.w};
        uint32_t hi[4], lo[4];
#pragma unroll
        for (int j = 0; j < 4; j++) {
            __nv_bfloat16 h0 = __float2bfloat16_rn(f[2 * j]);
            __nv_bfloat16 h1 = __float2bfloat16_rn(f[2 * j + 1]);
            __nv_bfloat16 l0 = __float2bfloat16_rn(f[2 * j]     - __bfloat162float(h0));
            __nv_bfloat16 l1 = __float2bfloat16_rn(f[2 * j + 1] - __bfloat162float(h1));
            hi[j] = (uint32_t)__bfloat16_as_ushort(h0) | ((uint32_t)__bfloat16_as_ushort(h1) << 16);
            lo[j] = (uint32_t)__bfloat16_as_ushort(l0) | ((uint32_t)__bfloat16_as_ushort(l1) << 16);
        }
        uint32_t off = (uint32_t)m * 256 + ((c ^ (m & 7)) << 4);
        *(uint4*)(smem + OFF_AH + off) = make_uint4(hi[0], hi[1], hi[2], hi[3]);
        *(uint4*)(smem + OFF_AL + off) = make_uint4(lo[0], lo[1], lo[2], lo[3]);
    }
    // ---- B: bulk copy pre-swizzled 32KB image for relation g ----
    {
        const uint4* src = (const uint4*)(Bimg + (size_t)g * 32768);
        uint4* dst = (uint4*)(smem + OFF_BH);
        for (int i = tid; i < 2048; i += 256) dst[i] = src[i];
    }
    __syncthreads();

    const int wm = wid >> 1;           // 0..3  (rows 32*wm)
    const int wn = wid & 1;            // 0..1  (cols 32*wn)
    const int mbase = wm * 32;
    const int nbase = wn * 32;

    float acc[2][4][4];
#pragma unroll
    for (int i = 0; i < 2; i++)
#pragma unroll
        for (int j = 0; j < 4; j++)
#pragma unroll
            for (int q = 0; q < 4; q++) acc[i][j][q] = 0.f;

    const uint32_t sb = smem_u32(smem);
    const int a_m  = mbase + (lane & 15);
    const int a_cb = lane >> 4;
    const int b_n  = nbase + (lane & 7) + ((lane >> 4) & 1) * 8;
    const int b_cb = (lane >> 3) & 1;

#pragma unroll
    for (int t = 0; t < 3; t++) {
        const uint32_t abase = sb + (t == 2 ? OFF_AL : OFF_AH);
        const uint32_t bbase = sb + (t == 1 ? OFF_BL : OFF_BH);
#pragma unroll
        for (int ks = 0; ks < 8; ks++) {
            const int c = ks * 2;
            uint32_t afr[2][4], bfr[2][4];
#pragma unroll
            for (int mt = 0; mt < 2; mt++) {
                int m = a_m + mt * 16, cc = c + a_cb;
                uint32_t ad = abase + (uint32_t)m * 256 + ((cc ^ (m & 7)) << 4);
                ldsm4(ad, afr[mt][0], afr[mt][1], afr[mt][2], afr[mt][3]);
            }
#pragma unroll
            for (int pr = 0; pr < 2; pr++) {
                int n = b_n + pr * 16, cc = c + b_cb;
                uint32_t bd = bbase + (uint32_t)n * 256 + ((cc ^ (n & 7)) << 4);
                ldsm4(bd, bfr[pr][0], bfr[pr][1], bfr[pr][2], bfr[pr][3]);
            }
#pragma unroll
            for (int mt = 0; mt < 2; mt++)
#pragma unroll
                for (int nt = 0; nt < 4; nt++)
                    mma_bf16(acc[mt][nt], afr[mt],
                             bfr[nt >> 1][(nt & 1) * 2],
                             bfr[nt >> 1][(nt & 1) * 2 + 1]);
        }
    }

    // ---- epilogue: direct float2 stores ----
    const int grp4 = lane >> 2, tg = lane & 3;
#pragma unroll
    for (int mt = 0; mt < 2; mt++)
#pragma unroll
        for (int nt = 0; nt < 4; nt++) {
            int row0 = m0 + mbase + mt * 16 + grp4;
            int col  = nbase + nt * 8 + tg * 2;
            if (row0 < M)
                *(float2*)&C[((size_t)g * M + row0) * OO + col] =
                    make_float2(acc[mt][nt][0], acc[mt][nt][1]);
            int row1 = row0 + 8;
            if (row1 < M)
                *(float2*)&C[((size_t)g * M + row1) * OO + col] =
                    make_float2(acc[mt][nt][2], acc[mt][nt][3]);
        }
}

// ---------------------------------------------------------------------------
// SpMM scatter: grid.y = relation. 16 lanes per edge, 2 edges per group (ILP).
// ---------------------------------------------------------------------------
__global__ void __launch_bounds__(256)
spmm_kernel(const int* __restrict__ rows,
            const int* __restrict__ cols,
            const float* __restrict__ vals,
            const float* __restrict__ tmp,
            float* __restrict__ z)
{
    const int r   = blockIdx.y;
    const int grp = threadIdx.x >> 4;
    const int l16 = threadIdx.x & 15;
    const int e   = blockIdx.x * 32 + grp * 2;
    const size_t eo = (size_t)r * EE + e;

    int2 rw = make_int2(0, 0), cl = make_int2(0, 0);
    float2 vv = make_float2(0.f, 0.f);
    if (l16 == 0) {
        rw = *(const int2*)(rows + eo);
        cl = *(const int2*)(cols + eo);
        vv = *(const float2*)(vals + eo);
    }
    int   row0 = __shfl_sync(0xffffffffu, rw.x, 0, 16);
    int   row1 = __shfl_sync(0xffffffffu, rw.y, 0, 16);
    int   col0 = __shfl_sync(0xffffffffu, cl.x, 0, 16);
    int   col1 = __shfl_sync(0xffffffffu, cl.y, 0, 16);
    float v0   = __shfl_sync(0xffffffffu, vv.x, 0, 16);
    float v1   = __shfl_sync(0xffffffffu, vv.y, 0, 16);

    const float4 t0 = __ldg((const float4*)(tmp + ((size_t)r * 100000 + col0) * OO) + l16);
    const float4 t1 = __ldg((const float4*)(tmp + ((size_t)r * 100000 + col1) * OO) + l16);

    float* d0 = z + (size_t)row0 * OO + (l16 << 2);
    float* d1 = z + (size_t)row1 * OO + (l16 << 2);
    asm volatile("red.global.add.v4.f32 [%0], {%1, %2, %3, %4};"
                 :: "l"(d0), "f"(t0.x * v0), "f"(t0.y * v0), "f"(t0.z * v0), "f"(t0.w * v0)
                 : "memory");
    asm volatile("red.global.add.v4.f32 [%0], {%1, %2, %3, %4};"
                 :: "l"(d1), "f"(t1.x * v1), "f"(t1.y * v1), "f"(t1.z * v1), "f"(t1.w * v1)
                 : "memory");
}

// ---------------------------------------------------------------------------
// zero / relu
// ---------------------------------------------------------------------------
__global__ void zero_kernel(float4* __restrict__ p, int n4)
{
    int i = blockIdx.x * blockDim.x + threadIdx.x;
    if (i < n4) p[i] = make_float4(0.f, 0.f, 0.f, 0.f);
}
__global__ void relu_kernel(float4* __restrict__ p, int n4)
{
    int i = blockIdx.x * blockDim.x + threadIdx.x;
    if (i < n4) {
        float4 v = p[i];
        v.x = fmaxf(v.x, 0.f); v.y = fmaxf(v.y, 0.f);
        v.z = fmaxf(v.z, 0.f); v.w = fmaxf(v.w, 0.f);
        p[i] = v;
    }
}

// ---------------------------------------------------------------------------
// kernel_launch
// ---------------------------------------------------------------------------
extern "C" void kernel_launch(void* const* d_in, const int* in_sizes, int n_in,
                              void* d_out, int out_size)
{
    const float* x_u  = (const float*)d_in[0];
    const float* x_v  = (const float*)d_in[1];
    const int*   srow = (const int*)d_in[2];
    const int*   scol = (const int*)d_in[3];
    const float* sval = (const float*)d_in[4];
    const float* wu   = (const float*)d_in[5];
    const float* wv   = (const float*)d_in[6];

    float* out = (float*)d_out;
    float* z_u = out;
    float* z_v = out + (size_t)NU * OO;

    float *tmpU, *tmpV;
    unsigned char *BiU, *BiV;
    cudaGetSymbolAddress((void**)&tmpU, g_tmpU);
    cudaGetSymbolAddress((void**)&tmpV, g_tmpV);
    cudaGetSymbolAddress((void**)&BiU, g_BimgU);
    cudaGetSymbolAddress((void**)&BiV, g_BimgV);

    cudaFuncSetAttribute(gemm_tc_kernel,
                         cudaFuncAttributeMaxDynamicSharedMemorySize, GT_SMEM);

    const int n4 = (NU * OO + NVV * OO) / 4;
    zero_kernel<<<(n4 + 255) / 256, 256>>>((float4*)out, n4);

    cumsum_pack_kernel<<<dim3((DD * OO + 255) / 256, 2), 256>>>(wu, wv, BiU, BiV);

    const dim3 gg(RR, (NU + 127) / 128);       // (5, 782)
    const dim3 sg(EE / 32, RR);                // (20000, 5)

    // v side: GEMM tmpV then scatter into z_u (tmpV hot in L2)
    gemm_tc_kernel<<<gg, 256, GT_SMEM>>>(x_v, BiV, tmpV, NVV);
    spmm_kernel<<<sg, 256>>>(srow, scol, sval, tmpV, z_u);

    // u side
    gemm_tc_kernel<<<gg, 256, GT_SMEM>>>(x_u, BiU, tmpU, NU);
    spmm_kernel<<<sg, 256>>>(scol, srow, sval, tmpU, z_v);

    relu_kernel<<<(n4 + 255) / 256, 256>>>((float4*)out, n4);
}